// round 7
// baseline (speedup 1.0000x reference)
#include <cuda_runtime.h>
#include <cuda_fp16.h>
#include <mma.h>
#include <math_constants.h>
#include <cooperative_groups.h>
#include <cstdint>

using namespace nvcuda;
namespace cg = cooperative_groups;

#define DD   128
#define MAXN 50048
#define MAXE 1600256

// ---------------- device scratch (no allocations allowed) ----------------
__device__ __align__(128) float g_K[MAXN * DD];
__device__ __align__(128) float g_Q[MAXN * DD];
__device__ __align__(128) float g_V[MAXN * DD];
__device__ int g_deg[MAXN];
__device__ int g_off[MAXN + 1];
__device__ int g_pos[MAXN];
__device__ int g_esrc[MAXE];

// ---------------- SMEM layout for proj (dynamic) ---------------------------
#define LDH    144                       // halves per row (pad 128+16)
#define S_AHI  0                         // 128*144*2 = 36864
#define S_ALO  36864
#define S_BHI  73728
#define S_BLO  110592
#define S_BIAS 147456                    // 128 floats
#define S_TOT  147968
#define LDO    132                       // fp32 out scratch leading dim

// split fp32 -> (hi, lo) fp16; store 4 consecutive k-columns
__device__ __forceinline__ void split_store4(__half* hi, __half* lo,
                                             int row, int c0, float4 v) {
    __half h0 = __float2half_rn(v.x), h1 = __float2half_rn(v.y);
    __half h2 = __float2half_rn(v.z), h3 = __float2half_rn(v.w);
    __half l0 = __float2half_rn(v.x - __half2float(h0));
    __half l1 = __float2half_rn(v.y - __half2float(h1));
    __half l2 = __float2half_rn(v.z - __half2float(h2));
    __half l3 = __float2half_rn(v.w - __half2float(h3));
    __half2 H01 = __halves2half2(h0, h1), H23 = __halves2half2(h2, h3);
    __half2 L01 = __halves2half2(l0, l1), L23 = __halves2half2(l2, l3);
    uint2 uh; uh.x = *(uint32_t*)&H01; uh.y = *(uint32_t*)&H23;
    uint2 ul; ul.x = *(uint32_t*)&L01; ul.y = *(uint32_t*)&L23;
    *(uint2*)&hi[row * LDH + c0] = uh;
    *(uint2*)&lo[row * LDH + c0] = ul;
}

// ---------------- projections via wmma (fp16-split, fp32 accum) ------------
__global__ void __launch_bounds__(256, 1)
proj_wmma(const float* __restrict__ X,
          const float* __restrict__ Wk, const float* __restrict__ bk,
          const float* __restrict__ Wq, const float* __restrict__ bq,
          const float* __restrict__ Wv, const float* __restrict__ bv,
          int n) {
    extern __shared__ char smem[];
    __half* sAhi = (__half*)(smem + S_AHI);
    __half* sAlo = (__half*)(smem + S_ALO);
    __half* sBhi = (__half*)(smem + S_BHI);
    __half* sBlo = (__half*)(smem + S_BLO);
    float*  sbias = (float*)(smem + S_BIAS);
    float*  sOut  = (float*)(smem + S_BHI);   // reused after MMA completes

    const int tid = threadIdx.x, wid = tid >> 5;
    const int wr = wid & 3, wc = wid >> 2;
    const int m0 = blockIdx.x * 128;

    // split X tile once
    for (int idx = tid; idx < 128 * 32; idx += 256) {
        int row = idx >> 5;
        int c0  = (idx & 31) << 2;
        int gr  = m0 + row;
        float4 v = (gr < n) ? *(const float4*)&X[(long)gr * DD + c0]
                            : make_float4(0.f, 0.f, 0.f, 0.f);
        split_store4(sAhi, sAlo, row, c0, v);
    }

    const float* Ws[3] = {Wk, Wq, Wv};
    const float* bs[3] = {bk, bq, bv};
    float* Ys[3] = {g_K, g_Q, g_V};

    for (int which = 0; which < 3; which++) {
        const float* W = Ws[which];
        for (int idx = tid; idx < 128 * 32; idx += 256) {
            int row = idx >> 5;
            int c0  = (idx & 31) << 2;
            float4 v = *(const float4*)&W[row * DD + c0];
            split_store4(sBhi, sBlo, row, c0, v);
        }
        if (tid < 128) sbias[tid] = bs[which][tid];
        __syncthreads();

        wmma::fragment<wmma::accumulator, 16, 16, 16, float> acc[2][4];
#pragma unroll
        for (int i = 0; i < 2; i++)
#pragma unroll
            for (int j = 0; j < 4; j++) wmma::fill_fragment(acc[i][j], 0.f);

#pragma unroll
        for (int k0 = 0; k0 < 128; k0 += 16) {
            wmma::fragment<wmma::matrix_a, 16, 16, 16, __half, wmma::row_major> ah[2], al[2];
#pragma unroll
            for (int i = 0; i < 2; i++) {
                wmma::load_matrix_sync(ah[i], sAhi + (wr * 32 + i * 16) * LDH + k0, LDH);
                wmma::load_matrix_sync(al[i], sAlo + (wr * 32 + i * 16) * LDH + k0, LDH);
            }
#pragma unroll
            for (int j = 0; j < 4; j++) {
                wmma::fragment<wmma::matrix_b, 16, 16, 16, __half, wmma::col_major> bh, bl;
                wmma::load_matrix_sync(bh, sBhi + (wc * 64 + j * 16) * LDH + k0, LDH);
                wmma::load_matrix_sync(bl, sBlo + (wc * 64 + j * 16) * LDH + k0, LDH);
#pragma unroll
                for (int i = 0; i < 2; i++) {
                    wmma::mma_sync(acc[i][j], ah[i], bh, acc[i][j]);
                    wmma::mma_sync(acc[i][j], ah[i], bl, acc[i][j]);
                    wmma::mma_sync(acc[i][j], al[i], bh, acc[i][j]);
                }
            }
        }

        __syncthreads();
#pragma unroll
        for (int i = 0; i < 2; i++)
#pragma unroll
            for (int j = 0; j < 4; j++)
                wmma::store_matrix_sync(&sOut[(wr * 32 + i * 16) * LDO + wc * 64 + j * 16],
                                        acc[i][j], LDO, wmma::mem_row_major);
        __syncthreads();

        float* __restrict__ Y = Ys[which];
        for (int idx = tid; idx < 128 * 32; idx += 256) {
            int row = idx >> 5;
            int c0  = (idx & 31) << 2;
            int gr  = m0 + row;
            if (gr < n) {
                float4 o = *(const float4*)&sOut[row * LDO + c0];
                o.x += sbias[c0 + 0]; o.y += sbias[c0 + 1];
                o.z += sbias[c0 + 2]; o.w += sbias[c0 + 3];
                *(float4*)&Y[(long)gr * DD + c0] = o;
            }
        }
        __syncthreads();
    }
}

// ---------------- CSR build: one cooperative kernel -------------------------
__global__ void __launch_bounds__(1024, 1)
csr_kernel(const int* __restrict__ src, const int* __restrict__ dst,
           int n, int E) {
    cg::grid_group grid = cg::this_grid();
    const int gt = blockIdx.x * 1024 + threadIdx.x;
    const int nt = gridDim.x * 1024;

    // phase 1: zero degree counters
    for (int i = gt; i < n; i += nt) g_deg[i] = 0;
    grid.sync();

    // phase 2: histogram
    for (int e = gt; e < E; e += nt) atomicAdd(&g_deg[dst[e]], 1);
    grid.sync();

    // phase 3: exclusive scan (block 0 only, 1024 threads)
    if (blockIdx.x == 0) {
        __shared__ int sums[1024];
        int tid   = threadIdx.x;
        int chunk = (n + 1023) >> 10;
        int start = tid * chunk;
        int endi  = min(start + chunk, n);
        int s = 0;
        for (int i = start; i < endi; i++) s += g_deg[i];
        sums[tid] = s;
        __syncthreads();
        if (tid == 0) {
            int run = 0;
            for (int i = 0; i < 1024; i++) { int t = sums[i]; sums[i] = run; run += t; }
        }
        __syncthreads();
        int run = sums[tid];
        for (int i = start; i < endi; i++) {
            g_off[i] = run;
            g_pos[i] = run;
            run += g_deg[i];
        }
        if (endi == n) g_off[n] = run;
    }
    grid.sync();

    // phase 4: fill
    for (int e = gt; e < E; e += nt) {
        int p = atomicAdd(&g_pos[dst[e]], 1);
        g_esrc[p] = src[e];
    }
}

// ---------------- fused edge-softmax + aggregate ---------------------------
// One warp per node. No online max (scores bounded ~32 -> exp safe in fp32,
// identical math to reference softmax). Depth-1 prefetch of K/V rows.
__global__ void aggregate_kernel(float* __restrict__ out, int n) {
    int gw   = (blockIdx.x * blockDim.x + threadIdx.x) >> 5;
    int lane = threadIdx.x & 31;
    if (gw >= n) return;

    const int beg = g_off[gw];
    const int end = g_off[gw + 1];

    const float4 q4 = *(const float4*)&g_Q[(long)gw * DD + lane * 4];

    float  d = 0.f;
    float4 acc = make_float4(0.f, 0.f, 0.f, 0.f);

    for (int e0 = beg; e0 < end; e0 += 32) {
        int mysrc = (e0 + lane < end) ? g_esrc[e0 + lane] : 0;
        int cnt   = min(32, end - e0);

        int s0 = __shfl_sync(0xffffffffu, mysrc, 0);
        float4 k = *(const float4*)&g_K[(long)s0 * DD + lane * 4];
        float4 v = *(const float4*)&g_V[(long)s0 * DD + lane * 4];

        for (int j = 0; j < cnt; j++) {
            float4 kc = k, vc = v;
            if (j + 1 < cnt) {
                int s2 = __shfl_sync(0xffffffffu, mysrc, j + 1);
                k = *(const float4*)&g_K[(long)s2 * DD + lane * 4];
                v = *(const float4*)&g_V[(long)s2 * DD + lane * 4];
            }
            float sc = kc.x * q4.x + kc.y * q4.y + kc.z * q4.z + kc.w * q4.w;
            sc += __shfl_xor_sync(0xffffffffu, sc, 1);
            sc += __shfl_xor_sync(0xffffffffu, sc, 2);
            sc += __shfl_xor_sync(0xffffffffu, sc, 4);

            float p = __expf(sc);
            d += p;
            acc.x = fmaf(p, vc.x, acc.x);
            acc.y = fmaf(p, vc.y, acc.y);
            acc.z = fmaf(p, vc.z, acc.z);
            acc.w = fmaf(p, vc.w, acc.w);
        }
    }

    float inv = (d > 0.f) ? (1.f / d) : 0.f;
    float4 o = make_float4(acc.x * inv, acc.y * inv, acc.z * inv, acc.w * inv);
    *(float4*)&out[(long)gw * DD + lane * 4] = o;
}

// ---------------- launch ----------------------------------------------------
extern "C" void kernel_launch(void* const* d_in, const int* in_sizes, int n_in,
                              void* d_out, int out_size) {
    const float* x  = (const float*)d_in[0];
    const float* Wk = (const float*)d_in[1];
    const float* bk = (const float*)d_in[2];
    const float* Wq = (const float*)d_in[3];
    const float* bq = (const float*)d_in[4];
    const float* Wv = (const float*)d_in[5];
    const float* bv = (const float*)d_in[6];
    const int*  src = (const int*)d_in[7];
    const int*  dst = (const int*)d_in[8];
    float* out = (float*)d_out;

    int n = in_sizes[0] / DD;   // 50000
    int E = in_sizes[7];        // 1600000

    cudaFuncSetAttribute(proj_wmma, cudaFuncAttributeMaxDynamicSharedMemorySize,
                         S_TOT);
    proj_wmma<<<(n + 127) / 128, 256, S_TOT>>>(x, Wk, bk, Wq, bq, Wv, bv, n);

    // cooperative CSR build (hist + scan + fill in one kernel)
    int dev = 0, nsm = 0, bpm = 0;
    cudaGetDevice(&dev);
    cudaDeviceGetAttribute(&nsm, cudaDevAttrMultiProcessorCount, dev);
    cudaOccupancyMaxActiveBlocksPerMultiprocessor(&bpm, csr_kernel, 1024, 0);
    if (bpm < 1) bpm = 1;
    void* args[4] = {(void*)&src, (void*)&dst, (void*)&n, (void*)&E};
    cudaLaunchCooperativeKernel((void*)csr_kernel, dim3(nsm * bpm), dim3(1024),
                                args, 0, (cudaStream_t)0);

    int totalThreads = n * 32;
    aggregate_kernel<<<(totalThreads + 255) / 256, 256>>>(out, n);
}

// round 8
// speedup vs baseline: 1.0010x; 1.0010x over previous
#include <cuda_runtime.h>
#include <cuda_fp16.h>
#include <mma.h>
#include <math_constants.h>
#include <cooperative_groups.h>
#include <cstdint>

using namespace nvcuda;
namespace cg = cooperative_groups;

#define DD   128
#define MAXN 50048
#define MAXE 1600256

// ---------------- device scratch (no allocations allowed) ----------------
__device__ __align__(128) float g_K[MAXN * DD];
__device__ __align__(128) float g_Q[MAXN * DD];
__device__ __align__(128) float g_V[MAXN * DD];
__device__ __align__(128) __half g_Whi[3 * DD * DD];
__device__ __align__(128) __half g_Wlo[3 * DD * DD];
__device__ int g_deg[MAXN];
__device__ int g_off[MAXN + 1];
__device__ int g_pos[MAXN];
__device__ int g_esrc[MAXE];

// ---------------- W pre-split: fp32 -> (hi, lo) fp16 ----------------------
// Layout matches wmma col_major matrix_b with ldb = 128: elem(k, c) = base + c*128 + k
// W is [c][k] row-major, i.e. W[c*128 + k] — identical indexing, direct copy.
__global__ void prep_w(const float* __restrict__ Wk,
                       const float* __restrict__ Wq,
                       const float* __restrict__ Wv) {
    int idx = blockIdx.x * blockDim.x + threadIdx.x;
    if (idx >= 3 * DD * DD) return;
    int which = idx / (DD * DD);
    int i     = idx - which * (DD * DD);
    const float* W = (which == 0) ? Wk : (which == 1) ? Wq : Wv;
    float v  = W[i];
    __half h = __float2half_rn(v);
    __half l = __float2half_rn(v - __half2float(h));
    g_Whi[idx] = h;
    g_Wlo[idx] = l;
}

// ---------------- projection via wmma, occupancy-optimized -----------------
// grid = (ceil(n/64), 3). CTA: 64-row M tile, one GEMM. 256 thr = 8 warps in
// a 2x4 grid; each warp owns 32 rows x 32 cols (2x2 m16n16k16 fragments).
// A (X tile) split hi/lo into smem; B (W splits) read straight from global
// (fully L1-resident: 64 KB/CTA, massively reused).
#define LDH  136                         // padded halves per A row
#define LDO  132                         // fp32 out scratch leading dim
#define SA_BYTES (64 * LDH * 2)          // 17408
#define PS_BIAS  (2 * SA_BYTES)          // after Ahi, Alo
#define PS_TOT   (PS_BIAS + 512)

__global__ void __launch_bounds__(256, 2)
proj_wmma(const float* __restrict__ X,
          const float* __restrict__ bk,
          const float* __restrict__ bq,
          const float* __restrict__ bv,
          int n) {
    extern __shared__ char smem[];
    __half* sAhi = (__half*)(smem);
    __half* sAlo = (__half*)(smem + SA_BYTES);
    float*  sbias = (float*)(smem + PS_BIAS);
    float*  sOut  = (float*)(smem);          // aliases A region after k-loop

    const int tid = threadIdx.x, wid = tid >> 5;
    const int wr = wid >> 2, wc = wid & 3;   // 2 x 4 warp grid
    const int which = blockIdx.y;
    const int m0 = blockIdx.x * 64;

    // zero g_deg once (only y==0 plane; 782*256 = 200k >= n)
    if (which == 0) {
        int gi = blockIdx.x * 256 + tid;
        if (gi < n) g_deg[gi] = 0;
    }

    // split X tile (64 x 128) into sAhi / sAlo
    for (int idx = tid; idx < 64 * 32; idx += 256) {
        int row = idx >> 5;
        int c0  = (idx & 31) << 2;
        int gr  = m0 + row;
        float4 v = (gr < n) ? *(const float4*)&X[(long)gr * DD + c0]
                            : make_float4(0.f, 0.f, 0.f, 0.f);
        __half h0 = __float2half_rn(v.x), h1 = __float2half_rn(v.y);
        __half h2 = __float2half_rn(v.z), h3 = __float2half_rn(v.w);
        __half l0 = __float2half_rn(v.x - __half2float(h0));
        __half l1 = __float2half_rn(v.y - __half2float(h1));
        __half l2 = __float2half_rn(v.z - __half2float(h2));
        __half l3 = __float2half_rn(v.w - __half2float(h3));
        __half2 H01 = __halves2half2(h0, h1), H23 = __halves2half2(h2, h3);
        __half2 L01 = __halves2half2(l0, l1), L23 = __halves2half2(l2, l3);
        uint2 uh; uh.x = *(uint32_t*)&H01; uh.y = *(uint32_t*)&H23;
        uint2 ul; ul.x = *(uint32_t*)&L01; ul.y = *(uint32_t*)&L23;
        *(uint2*)&sAhi[row * LDH + c0] = uh;
        *(uint2*)&sAlo[row * LDH + c0] = ul;
    }
    {
        const float* b = (which == 0) ? bk : (which == 1) ? bq : bv;
        if (tid < 128) sbias[tid] = b[tid];
    }
    __syncthreads();

    const __half* Bhi = g_Whi + which * (DD * DD);
    const __half* Blo = g_Wlo + which * (DD * DD);

    wmma::fragment<wmma::accumulator, 16, 16, 16, float> acc[2][2];
#pragma unroll
    for (int i = 0; i < 2; i++)
#pragma unroll
        for (int j = 0; j < 2; j++) wmma::fill_fragment(acc[i][j], 0.f);

#pragma unroll
    for (int k0 = 0; k0 < 128; k0 += 16) {
        wmma::fragment<wmma::matrix_a, 16, 16, 16, __half, wmma::row_major> ah[2], al[2];
#pragma unroll
        for (int i = 0; i < 2; i++) {
            wmma::load_matrix_sync(ah[i], sAhi + (wr * 32 + i * 16) * LDH + k0, LDH);
            wmma::load_matrix_sync(al[i], sAlo + (wr * 32 + i * 16) * LDH + k0, LDH);
        }
#pragma unroll
        for (int j = 0; j < 2; j++) {
            wmma::fragment<wmma::matrix_b, 16, 16, 16, __half, wmma::col_major> bh, bl;
            wmma::load_matrix_sync(bh, Bhi + (wc * 32 + j * 16) * DD + k0, DD);
            wmma::load_matrix_sync(bl, Blo + (wc * 32 + j * 16) * DD + k0, DD);
#pragma unroll
            for (int i = 0; i < 2; i++) {
                wmma::mma_sync(acc[i][j], ah[i], bh, acc[i][j]);
                wmma::mma_sync(acc[i][j], ah[i], bl, acc[i][j]);
                wmma::mma_sync(acc[i][j], al[i], bh, acc[i][j]);
            }
        }
    }

    __syncthreads();   // done reading sA; reuse as sOut
#pragma unroll
    for (int i = 0; i < 2; i++)
#pragma unroll
        for (int j = 0; j < 2; j++)
            wmma::store_matrix_sync(&sOut[(wr * 32 + i * 16) * LDO + wc * 32 + j * 16],
                                    acc[i][j], LDO, wmma::mem_row_major);
    __syncthreads();

    float* __restrict__ Y = (which == 0) ? g_K : (which == 1) ? g_Q : g_V;
    for (int idx = tid; idx < 64 * 32; idx += 256) {
        int row = idx >> 5;
        int c0  = (idx & 31) << 2;
        int gr  = m0 + row;
        if (gr < n) {
            float4 o = *(const float4*)&sOut[row * LDO + c0];
            o.x += sbias[c0 + 0]; o.y += sbias[c0 + 1];
            o.z += sbias[c0 + 2]; o.w += sbias[c0 + 3];
            *(float4*)&Y[(long)gr * DD + c0] = o;
        }
    }
}

// ---------------- CSR build: one cooperative kernel (unchanged r7) ---------
__global__ void __launch_bounds__(1024, 1)
csr_kernel(const int* __restrict__ src, const int* __restrict__ dst,
           int n, int E) {
    cg::grid_group grid = cg::this_grid();
    const int gt = blockIdx.x * 1024 + threadIdx.x;
    const int nt = gridDim.x * 1024;

    // g_deg already zeroed by proj_wmma
    for (int e = gt; e < E; e += nt) atomicAdd(&g_deg[dst[e]], 1);
    grid.sync();

    if (blockIdx.x == 0) {
        __shared__ int sums[1024];
        int tid   = threadIdx.x;
        int chunk = (n + 1023) >> 10;
        int start = tid * chunk;
        int endi  = min(start + chunk, n);
        int s = 0;
        for (int i = start; i < endi; i++) s += g_deg[i];
        sums[tid] = s;
        __syncthreads();
        if (tid == 0) {
            int run = 0;
            for (int i = 0; i < 1024; i++) { int t = sums[i]; sums[i] = run; run += t; }
        }
        __syncthreads();
        int run = sums[tid];
        for (int i = start; i < endi; i++) {
            g_off[i] = run;
            g_pos[i] = run;
            run += g_deg[i];
        }
        if (endi == n) g_off[n] = run;
    }
    grid.sync();

    for (int e = gt; e < E; e += nt) {
        int p = atomicAdd(&g_pos[dst[e]], 1);
        g_esrc[p] = src[e];
    }
}

// ---------------- fused edge-softmax + aggregate (unchanged r7) ------------
__global__ void aggregate_kernel(float* __restrict__ out, int n) {
    int gw   = (blockIdx.x * blockDim.x + threadIdx.x) >> 5;
    int lane = threadIdx.x & 31;
    if (gw >= n) return;

    const int beg = g_off[gw];
    const int end = g_off[gw + 1];

    const float4 q4 = *(const float4*)&g_Q[(long)gw * DD + lane * 4];

    float  d = 0.f;
    float4 acc = make_float4(0.f, 0.f, 0.f, 0.f);

    for (int e0 = beg; e0 < end; e0 += 32) {
        int mysrc = (e0 + lane < end) ? g_esrc[e0 + lane] : 0;
        int cnt   = min(32, end - e0);

        int s0 = __shfl_sync(0xffffffffu, mysrc, 0);
        float4 k = *(const float4*)&g_K[(long)s0 * DD + lane * 4];
        float4 v = *(const float4*)&g_V[(long)s0 * DD + lane * 4];

        for (int j = 0; j < cnt; j++) {
            float4 kc = k, vc = v;
            if (j + 1 < cnt) {
                int s2 = __shfl_sync(0xffffffffu, mysrc, j + 1);
                k = *(const float4*)&g_K[(long)s2 * DD + lane * 4];
                v = *(const float4*)&g_V[(long)s2 * DD + lane * 4];
            }
            float sc = kc.x * q4.x + kc.y * q4.y + kc.z * q4.z + kc.w * q4.w;
            sc += __shfl_xor_sync(0xffffffffu, sc, 1);
            sc += __shfl_xor_sync(0xffffffffu, sc, 2);
            sc += __shfl_xor_sync(0xffffffffu, sc, 4);

            float p = __expf(sc);
            d += p;
            acc.x = fmaf(p, vc.x, acc.x);
            acc.y = fmaf(p, vc.y, acc.y);
            acc.z = fmaf(p, vc.z, acc.z);
            acc.w = fmaf(p, vc.w, acc.w);
        }
    }

    float inv = (d > 0.f) ? (1.f / d) : 0.f;
    float4 o = make_float4(acc.x * inv, acc.y * inv, acc.z * inv, acc.w * inv);
    *(float4*)&out[(long)gw * DD + lane * 4] = o;
}

// ---------------- launch ----------------------------------------------------
extern "C" void kernel_launch(void* const* d_in, const int* in_sizes, int n_in,
                              void* d_out, int out_size) {
    const float* x  = (const float*)d_in[0];
    const float* Wk = (const float*)d_in[1];
    const float* bk = (const float*)d_in[2];
    const float* Wq = (const float*)d_in[3];
    const float* bq = (const float*)d_in[4];
    const float* Wv = (const float*)d_in[5];
    const float* bv = (const float*)d_in[6];
    const int*  src = (const int*)d_in[7];
    const int*  dst = (const int*)d_in[8];
    float* out = (float*)d_out;

    int n = in_sizes[0] / DD;   // 50000
    int E = in_sizes[7];        // 1600000

    prep_w<<<(3 * DD * DD + 255) / 256, 256>>>(Wk, Wq, Wv);

    dim3 pg((n + 63) / 64, 3);
    proj_wmma<<<pg, 256, PS_TOT>>>(x, bk, bq, bv, n);

    // cooperative CSR build
    int dev = 0, nsm = 0, bpm = 0;
    cudaGetDevice(&dev);
    cudaDeviceGetAttribute(&nsm, cudaDevAttrMultiProcessorCount, dev);
    cudaOccupancyMaxActiveBlocksPerMultiprocessor(&bpm, csr_kernel, 1024, 0);
    if (bpm < 1) bpm = 1;
    void* args[4] = {(void*)&src, (void*)&dst, (void*)&n, (void*)&E};
    cudaLaunchCooperativeKernel((void*)csr_kernel, dim3(nsm * bpm), dim3(1024),
                                args, 0, (cudaStream_t)0);

    int totalThreads = n * 32;
    aggregate_kernel<<<(totalThreads + 255) / 256, 256>>>(out, n);
}

// round 9
// speedup vs baseline: 1.1822x; 1.1811x over previous
#include <cuda_runtime.h>
#include <cuda_fp16.h>
#include <mma.h>
#include <math_constants.h>
#include <cstdint>

using namespace nvcuda;

#define DD   128
#define MAXN 50048
#define MAXE 1600256

// ---------------- device scratch (no allocations allowed) ----------------
__device__ __align__(128) float g_K[MAXN * DD];
__device__ __align__(128) float g_Q[MAXN * DD];
__device__ __align__(128) float g_V[MAXN * DD];
__device__ __align__(128) __half g_Whi[3 * DD * DD];
__device__ __align__(128) __half g_Wlo[3 * DD * DD];
__device__ int g_deg[MAXN];
__device__ int g_off[MAXN + 1];
__device__ int g_pos[MAXN];
__device__ int g_esrc[MAXE];        // BYTE offsets (src * 512)

// ---------------- W pre-split: fp32 -> (hi, lo) fp16 ----------------------
__global__ void prep_w(const float* __restrict__ Wk,
                       const float* __restrict__ Wq,
                       const float* __restrict__ Wv) {
    int idx = blockIdx.x * blockDim.x + threadIdx.x;
    if (idx >= 3 * DD * DD) return;
    int which = idx / (DD * DD);
    int i     = idx - which * (DD * DD);
    const float* W = (which == 0) ? Wk : (which == 1) ? Wq : Wv;
    float v  = W[i];
    __half h = __float2half_rn(v);
    __half l = __float2half_rn(v - __half2float(h));
    g_Whi[idx] = h;
    g_Wlo[idx] = l;
}

// ---------------- projection via wmma, 2 CTAs/SM ---------------------------
// grid = (ceil(n/64), 3). CTA: 64-row tile x one GEMM. 8 warps = 2x4 grid,
// warp tile 32x32 (2x2 frags). A split in smem (64 rows); B split copied
// from pre-split global into smem (LDSM path). ~105 KB smem -> 2 CTAs/SM.
#define LDH  136
#define LDO  132
#define SA_BYTES  (64 * LDH * 2)              // 17408
#define SB_BYTES  (128 * LDH * 2)             // 34816
#define PS_AHI    0
#define PS_ALO    (SA_BYTES)
#define PS_BHI    (2 * SA_BYTES)
#define PS_BLO    (2 * SA_BYTES + SB_BYTES)
#define PS_TOT    (2 * SA_BYTES + 2 * SB_BYTES)   // 104448

__global__ void __launch_bounds__(256, 2)
proj_wmma(const float* __restrict__ X,
          const float* __restrict__ bk,
          const float* __restrict__ bq,
          const float* __restrict__ bv,
          int n) {
    extern __shared__ char smem[];
    __half* sAhi = (__half*)(smem + PS_AHI);
    __half* sAlo = (__half*)(smem + PS_ALO);
    __half* sBhi = (__half*)(smem + PS_BHI);
    __half* sBlo = (__half*)(smem + PS_BLO);
    float*  sOut = (float*)(smem);            // aliases A after k-loop

    const int tid = threadIdx.x, wid = tid >> 5;
    const int wr = wid >> 2, wc = wid & 3;    // 2 x 4 warp grid
    const int which = blockIdx.y;
    const int m0 = blockIdx.x * 64;

    if (which == 0) {                          // zero g_deg for hist
        int gi = blockIdx.x * 256 + tid;
        if (gi < n) g_deg[gi] = 0;
    }

    // split X tile (64 x 128) into sAhi / sAlo
    for (int idx = tid; idx < 64 * 32; idx += 256) {
        int row = idx >> 5;
        int c0  = (idx & 31) << 2;
        int gr  = m0 + row;
        float4 v = (gr < n) ? *(const float4*)&X[(long)gr * DD + c0]
                            : make_float4(0.f, 0.f, 0.f, 0.f);
        __half h0 = __float2half_rn(v.x), h1 = __float2half_rn(v.y);
        __half h2 = __float2half_rn(v.z), h3 = __float2half_rn(v.w);
        __half l0 = __float2half_rn(v.x - __half2float(h0));
        __half l1 = __float2half_rn(v.y - __half2float(h1));
        __half l2 = __float2half_rn(v.z - __half2float(h2));
        __half l3 = __float2half_rn(v.w - __half2float(h3));
        __half2 H01 = __halves2half2(h0, h1), H23 = __halves2half2(h2, h3);
        __half2 L01 = __halves2half2(l0, l1), L23 = __halves2half2(l2, l3);
        uint2 uh; uh.x = *(uint32_t*)&H01; uh.y = *(uint32_t*)&H23;
        uint2 ul; ul.x = *(uint32_t*)&L01; ul.y = *(uint32_t*)&L23;
        *(uint2*)&sAhi[row * LDH + c0] = uh;
        *(uint2*)&sAlo[row * LDH + c0] = ul;
    }

    // copy pre-split W (hi/lo) into smem: 128 rows x 128 halves, uint4 chunks
    {
        const uint4* ghi = (const uint4*)(g_Whi + which * (DD * DD));
        const uint4* glo = (const uint4*)(g_Wlo + which * (DD * DD));
        for (int idx = tid; idx < 128 * 16; idx += 256) {
            int c  = idx >> 4;
            int kq = (idx & 15) << 3;           // halves
            uint4 vh = ghi[idx];
            uint4 vl = glo[idx];
            *(uint4*)&sBhi[c * LDH + kq] = vh;
            *(uint4*)&sBlo[c * LDH + kq] = vl;
        }
    }
    __syncthreads();

    wmma::fragment<wmma::accumulator, 16, 16, 16, float> acc[2][2];
#pragma unroll
    for (int i = 0; i < 2; i++)
#pragma unroll
        for (int j = 0; j < 2; j++) wmma::fill_fragment(acc[i][j], 0.f);

#pragma unroll
    for (int k0 = 0; k0 < 128; k0 += 16) {
        wmma::fragment<wmma::matrix_a, 16, 16, 16, __half, wmma::row_major> ah[2], al[2];
#pragma unroll
        for (int i = 0; i < 2; i++) {
            wmma::load_matrix_sync(ah[i], sAhi + (wr * 32 + i * 16) * LDH + k0, LDH);
            wmma::load_matrix_sync(al[i], sAlo + (wr * 32 + i * 16) * LDH + k0, LDH);
        }
#pragma unroll
        for (int j = 0; j < 2; j++) {
            wmma::fragment<wmma::matrix_b, 16, 16, 16, __half, wmma::col_major> bh, bl;
            wmma::load_matrix_sync(bh, sBhi + (wc * 32 + j * 16) * LDH + k0, LDH);
            wmma::load_matrix_sync(bl, sBlo + (wc * 32 + j * 16) * LDH + k0, LDH);
#pragma unroll
            for (int i = 0; i < 2; i++) {
                wmma::mma_sync(acc[i][j], ah[i], bh, acc[i][j]);
                wmma::mma_sync(acc[i][j], ah[i], bl, acc[i][j]);
                wmma::mma_sync(acc[i][j], al[i], bh, acc[i][j]);
            }
        }
    }

    __syncthreads();   // done reading sA; reuse as sOut
#pragma unroll
    for (int i = 0; i < 2; i++)
#pragma unroll
        for (int j = 0; j < 2; j++)
            wmma::store_matrix_sync(&sOut[(wr * 32 + i * 16) * LDO + wc * 32 + j * 16],
                                    acc[i][j], LDO, wmma::mem_row_major);
    __syncthreads();

    const float* b = (which == 0) ? bk : (which == 1) ? bq : bv;
    float* __restrict__ Y = (which == 0) ? g_K : (which == 1) ? g_Q : g_V;
    for (int idx = tid; idx < 64 * 32; idx += 256) {
        int row = idx >> 5;
        int c0  = (idx & 31) << 2;
        int gr  = m0 + row;
        if (gr < n) {
            float4 o  = *(const float4*)&sOut[row * LDO + c0];
            float4 bb = *(const float4*)&b[c0];
            o.x += bb.x; o.y += bb.y; o.z += bb.z; o.w += bb.w;
            *(float4*)&Y[(long)gr * DD + c0] = o;
        }
    }
}

// ---------------- CSR build (split kernels, known-good) ---------------------
__global__ void hist_kernel(const int* __restrict__ dst, int E) {
    int e = blockIdx.x * blockDim.x + threadIdx.x;
    if (e < E) atomicAdd(&g_deg[dst[e]], 1);
}

__global__ void scan_kernel(int n) {
    __shared__ int sums[1024];
    int tid   = threadIdx.x;
    int chunk = (n + 1023) >> 10;
    int start = tid * chunk;
    int endi  = min(start + chunk, n);
    int s = 0;
    for (int i = start; i < endi; i++) s += g_deg[i];
    sums[tid] = s;
    __syncthreads();
    if (tid == 0) {
        int run = 0;
        for (int i = 0; i < 1024; i++) { int t = sums[i]; sums[i] = run; run += t; }
    }
    __syncthreads();
    int run = sums[tid];
    for (int i = start; i < endi; i++) {
        g_off[i] = run;
        g_pos[i] = run;
        run += g_deg[i];
    }
    if (endi == n) g_off[n] = run;
}

__global__ void fill_kernel(const int* __restrict__ src,
                            const int* __restrict__ dst, int E) {
    int e = blockIdx.x * blockDim.x + threadIdx.x;
    if (e < E) {
        int p = atomicAdd(&g_pos[dst[e]], 1);
        g_esrc[p] = src[e] << 9;     // byte offset: src * 128 floats * 4 B
    }
}

// ---------------- fused edge-softmax + aggregate (instruction-lean) --------
// One warp per node; no online max (scores bounded ~32, exp safe in fp32 —
// identical math to reference softmax). Byte offsets pre-scaled; unroll-8
// with SEL-predicated tail (invalid lanes read row 0, p forced to 0).
__global__ void aggregate_kernel(float* __restrict__ out, int n) {
    int gw   = (blockIdx.x * blockDim.x + threadIdx.x) >> 5;
    int lane = threadIdx.x & 31;
    if (gw >= n) return;

    const int beg = g_off[gw];
    const int end = g_off[gw + 1];

    const char* Kb = (const char*)g_K + lane * 16;
    const char* Vb = (const char*)g_V + lane * 16;
    const float4 q4 = *(const float4*)&g_Q[(long)gw * DD + lane * 4];

    float  d = 0.f;
    float4 acc = make_float4(0.f, 0.f, 0.f, 0.f);

    for (int e0 = beg; e0 < end; e0 += 32) {
        int myoff = (e0 + lane < end) ? g_esrc[e0 + lane] : 0;
        int cnt   = min(32, end - e0);

        for (int b = 0; b < cnt; b += 8) {
#pragma unroll
            for (int j = 0; j < 8; j++) {
                int off = __shfl_sync(0xffffffffu, myoff, b + j);
                const float4 k4 = *(const float4*)(Kb + off);
                float sc = k4.x * q4.x + k4.y * q4.y + k4.z * q4.z + k4.w * q4.w;
                sc += __shfl_xor_sync(0xffffffffu, sc, 1);
                sc += __shfl_xor_sync(0xffffffffu, sc, 2);
                sc += __shfl_xor_sync(0xffffffffu, sc, 4);
                float p = __expf(sc);
                p = (b + j < cnt) ? p : 0.f;
                const float4 v4 = *(const float4*)(Vb + off);
                d += p;
                acc.x = fmaf(p, v4.x, acc.x);
                acc.y = fmaf(p, v4.y, acc.y);
                acc.z = fmaf(p, v4.z, acc.z);
                acc.w = fmaf(p, v4.w, acc.w);
            }
        }
    }

    float inv = (d > 0.f) ? (1.f / d) : 0.f;
    float4 o = make_float4(acc.x * inv, acc.y * inv, acc.z * inv, acc.w * inv);
    *(float4*)&out[(long)gw * DD + lane * 4] = o;
}

// ---------------- launch ----------------------------------------------------
extern "C" void kernel_launch(void* const* d_in, const int* in_sizes, int n_in,
                              void* d_out, int out_size) {
    const float* x  = (const float*)d_in[0];
    const float* Wk = (const float*)d_in[1];
    const float* bk = (const float*)d_in[2];
    const float* Wq = (const float*)d_in[3];
    const float* bq = (const float*)d_in[4];
    const float* Wv = (const float*)d_in[5];
    const float* bv = (const float*)d_in[6];
    const int*  src = (const int*)d_in[7];
    const int*  dst = (const int*)d_in[8];
    float* out = (float*)d_out;

    int n = in_sizes[0] / DD;   // 50000
    int E = in_sizes[7];        // 1600000

    prep_w<<<(3 * DD * DD + 255) / 256, 256>>>(Wk, Wq, Wv);

    cudaFuncSetAttribute(proj_wmma, cudaFuncAttributeMaxDynamicSharedMemorySize,
                         PS_TOT);
    dim3 pg((n + 63) / 64, 3);
    proj_wmma<<<pg, 256, PS_TOT>>>(x, bk, bq, bv, n);

    hist_kernel<<<(E + 255) / 256, 256>>>(dst, E);
    scan_kernel<<<1, 1024>>>(n);
    fill_kernel<<<(E + 255) / 256, 256>>>(src, dst, E);

    int totalThreads = n * 32;
    aggregate_kernel<<<(totalThreads + 255) / 256, 256>>>(out, n);
}

// round 10
// speedup vs baseline: 1.1983x; 1.0136x over previous
#include <cuda_runtime.h>
#include <cuda_fp16.h>
#include <mma.h>
#include <math_constants.h>
#include <cstdint>

using namespace nvcuda;

#define DD   128
#define MAXN 50048
#define MAXE 1600256

// ---------------- device scratch (no allocations allowed) ----------------
__device__ __align__(128) float g_K[MAXN * DD];
__device__ __align__(128) float g_Q[MAXN * DD];
__device__ __align__(128) float g_V[MAXN * DD];
__device__ __align__(128) __half g_Whi[3 * DD * DD];
__device__ __align__(128) __half g_Wlo[3 * DD * DD];
__device__ int g_deg[MAXN];
__device__ int g_off[MAXN + 1];
__device__ int g_pos[MAXN];
__device__ int g_esrc[MAXE];        // BYTE offsets (src * 512)
__device__ int g_chain[64];         // chained-scan flags (prefix+1; 0 = not ready)

// ---------------- W pre-split: fp32 -> (hi, lo) fp16 ----------------------
__global__ void prep_w(const float* __restrict__ Wk,
                       const float* __restrict__ Wq,
                       const float* __restrict__ Wv) {
    int idx = blockIdx.x * blockDim.x + threadIdx.x;
    if (idx >= 3 * DD * DD) return;
    int which = idx / (DD * DD);
    int i     = idx - which * (DD * DD);
    const float* W = (which == 0) ? Wk : (which == 1) ? Wq : Wv;
    float v  = W[i];
    __half h = __float2half_rn(v);
    __half l = __float2half_rn(v - __half2float(h));
    g_Whi[idx] = h;
    g_Wlo[idx] = l;
}

// ---------------- projection via wmma, 2 CTAs/SM (unchanged r9) ------------
#define LDH  136
#define LDO  132
#define SA_BYTES  (64 * LDH * 2)
#define SB_BYTES  (128 * LDH * 2)
#define PS_AHI    0
#define PS_ALO    (SA_BYTES)
#define PS_BHI    (2 * SA_BYTES)
#define PS_BLO    (2 * SA_BYTES + SB_BYTES)
#define PS_TOT    (2 * SA_BYTES + 2 * SB_BYTES)

__global__ void __launch_bounds__(256, 2)
proj_wmma(const float* __restrict__ X,
          const float* __restrict__ bk,
          const float* __restrict__ bq,
          const float* __restrict__ bv,
          int n) {
    extern __shared__ char smem[];
    __half* sAhi = (__half*)(smem + PS_AHI);
    __half* sAlo = (__half*)(smem + PS_ALO);
    __half* sBhi = (__half*)(smem + PS_BHI);
    __half* sBlo = (__half*)(smem + PS_BLO);
    float*  sOut = (float*)(smem);

    const int tid = threadIdx.x, wid = tid >> 5;
    const int wr = wid >> 2, wc = wid & 3;
    const int which = blockIdx.y;
    const int m0 = blockIdx.x * 64;

    if (which == 0) {
        int gi = blockIdx.x * 256 + tid;
        if (gi < n) g_deg[gi] = 0;
    }

    for (int idx = tid; idx < 64 * 32; idx += 256) {
        int row = idx >> 5;
        int c0  = (idx & 31) << 2;
        int gr  = m0 + row;
        float4 v = (gr < n) ? *(const float4*)&X[(long)gr * DD + c0]
                            : make_float4(0.f, 0.f, 0.f, 0.f);
        __half h0 = __float2half_rn(v.x), h1 = __float2half_rn(v.y);
        __half h2 = __float2half_rn(v.z), h3 = __float2half_rn(v.w);
        __half l0 = __float2half_rn(v.x - __half2float(h0));
        __half l1 = __float2half_rn(v.y - __half2float(h1));
        __half l2 = __float2half_rn(v.z - __half2float(h2));
        __half l3 = __float2half_rn(v.w - __half2float(h3));
        __half2 H01 = __halves2half2(h0, h1), H23 = __halves2half2(h2, h3);
        __half2 L01 = __halves2half2(l0, l1), L23 = __halves2half2(l2, l3);
        uint2 uh; uh.x = *(uint32_t*)&H01; uh.y = *(uint32_t*)&H23;
        uint2 ul; ul.x = *(uint32_t*)&L01; ul.y = *(uint32_t*)&L23;
        *(uint2*)&sAhi[row * LDH + c0] = uh;
        *(uint2*)&sAlo[row * LDH + c0] = ul;
    }

    {
        const uint4* ghi = (const uint4*)(g_Whi + which * (DD * DD));
        const uint4* glo = (const uint4*)(g_Wlo + which * (DD * DD));
        for (int idx = tid; idx < 128 * 16; idx += 256) {
            int c  = idx >> 4;
            int kq = (idx & 15) << 3;
            uint4 vh = ghi[idx];
            uint4 vl = glo[idx];
            *(uint4*)&sBhi[c * LDH + kq] = vh;
            *(uint4*)&sBlo[c * LDH + kq] = vl;
        }
    }
    __syncthreads();

    wmma::fragment<wmma::accumulator, 16, 16, 16, float> acc[2][2];
#pragma unroll
    for (int i = 0; i < 2; i++)
#pragma unroll
        for (int j = 0; j < 2; j++) wmma::fill_fragment(acc[i][j], 0.f);

#pragma unroll
    for (int k0 = 0; k0 < 128; k0 += 16) {
        wmma::fragment<wmma::matrix_a, 16, 16, 16, __half, wmma::row_major> ah[2], al[2];
#pragma unroll
        for (int i = 0; i < 2; i++) {
            wmma::load_matrix_sync(ah[i], sAhi + (wr * 32 + i * 16) * LDH + k0, LDH);
            wmma::load_matrix_sync(al[i], sAlo + (wr * 32 + i * 16) * LDH + k0, LDH);
        }
#pragma unroll
        for (int j = 0; j < 2; j++) {
            wmma::fragment<wmma::matrix_b, 16, 16, 16, __half, wmma::col_major> bh, bl;
            wmma::load_matrix_sync(bh, sBhi + (wc * 32 + j * 16) * LDH + k0, LDH);
            wmma::load_matrix_sync(bl, sBlo + (wc * 32 + j * 16) * LDH + k0, LDH);
#pragma unroll
            for (int i = 0; i < 2; i++) {
                wmma::mma_sync(acc[i][j], ah[i], bh, acc[i][j]);
                wmma::mma_sync(acc[i][j], ah[i], bl, acc[i][j]);
                wmma::mma_sync(acc[i][j], al[i], bh, acc[i][j]);
            }
        }
    }

    __syncthreads();
#pragma unroll
    for (int i = 0; i < 2; i++)
#pragma unroll
        for (int j = 0; j < 2; j++)
            wmma::store_matrix_sync(&sOut[(wr * 32 + i * 16) * LDO + wc * 32 + j * 16],
                                    acc[i][j], LDO, wmma::mem_row_major);
    __syncthreads();

    const float* b = (which == 0) ? bk : (which == 1) ? bq : bv;
    float* __restrict__ Y = (which == 0) ? g_K : (which == 1) ? g_Q : g_V;
    for (int idx = tid; idx < 64 * 32; idx += 256) {
        int row = idx >> 5;
        int c0  = (idx & 31) << 2;
        int gr  = m0 + row;
        if (gr < n) {
            float4 o  = *(const float4*)&sOut[row * LDO + c0];
            float4 bb = *(const float4*)&b[c0];
            o.x += bb.x; o.y += bb.y; o.z += bb.z; o.w += bb.w;
            *(float4*)&Y[(long)gr * DD + c0] = o;
        }
    }
}

// ---------------- CSR build -----------------------------------------------
__global__ void hist_kernel(const int* __restrict__ dst, int E) {
    int e = blockIdx.x * blockDim.x + threadIdx.x;
    if (e < 64) g_chain[e] = 0;          // reset chained-scan flags each run
    if (e < E) atomicAdd(&g_deg[dst[e]], 1);
}

// single-pass chained scan: 49 blocks x 1024 threads, block b waits on b-1.
__global__ void __launch_bounds__(1024, 1)
scan_chain_kernel(int n) {
    __shared__ int wsum[32];
    __shared__ int s_total, s_prefix;

    const int tid  = threadIdx.x;
    const int lane = tid & 31, warp = tid >> 5;
    const int i    = blockIdx.x * 1024 + tid;

    int v = (i < n) ? g_deg[i] : 0;

    // warp inclusive scan
    int inc = v;
#pragma unroll
    for (int o = 1; o < 32; o <<= 1) {
        int t = __shfl_up_sync(0xffffffffu, inc, o);
        if (lane >= o) inc += t;
    }
    if (lane == 31) wsum[warp] = inc;
    __syncthreads();

    // warp 0 scans the 32 warp totals -> exclusive prefixes + block total
    if (warp == 0) {
        int w  = wsum[lane];
        int wi = w;
#pragma unroll
        for (int o = 1; o < 32; o <<= 1) {
            int t = __shfl_up_sync(0xffffffffu, wi, o);
            if (lane >= o) wi += t;
        }
        wsum[lane] = wi - w;              // exclusive warp prefix
        if (lane == 31) s_total = wi;     // block total
    }
    __syncthreads();

    const int excl = (inc - v) + wsum[warp];   // exclusive within block

    // chain: acquire prefix from block b-1, publish inclusive prefix
    if (tid == 0) {
        int prefix = 0;
        if (blockIdx.x > 0) {
            int f;
            do { f = atomicAdd(&g_chain[blockIdx.x - 1], 0); } while (f == 0);
            prefix = f - 1;
        }
        atomicExch(&g_chain[blockIdx.x], prefix + s_total + 1);
        s_prefix = prefix;
    }
    __syncthreads();

    if (i < n) {
        int o = s_prefix + excl;
        g_off[i] = o;
        g_pos[i] = o;
    }
    if (blockIdx.x == gridDim.x - 1 && tid == 0)
        g_off[n] = s_prefix + s_total;
}

__global__ void fill_kernel(const int* __restrict__ src,
                            const int* __restrict__ dst, int E) {
    int e = blockIdx.x * blockDim.x + threadIdx.x;
    if (e < E) {
        int p = atomicAdd(&g_pos[dst[e]], 1);
        g_esrc[p] = src[e] << 9;     // byte offset: src * 128 floats * 4 B
    }
}

// ---------------- fused edge-softmax + aggregate (unchanged r9) ------------
__global__ void aggregate_kernel(float* __restrict__ out, int n) {
    int gw   = (blockIdx.x * blockDim.x + threadIdx.x) >> 5;
    int lane = threadIdx.x & 31;
    if (gw >= n) return;

    const int beg = g_off[gw];
    const int end = g_off[gw + 1];

    const char* Kb = (const char*)g_K + lane * 16;
    const char* Vb = (const char*)g_V + lane * 16;
    const float4 q4 = *(const float4*)&g_Q[(long)gw * DD + lane * 4];

    float  d = 0.f;
    float4 acc = make_float4(0.f, 0.f, 0.f, 0.f);

    for (int e0 = beg; e0 < end; e0 += 32) {
        int myoff = (e0 + lane < end) ? g_esrc[e0 + lane] : 0;
        int cnt   = min(32, end - e0);

        for (int b = 0; b < cnt; b += 8) {
#pragma unroll
            for (int j = 0; j < 8; j++) {
                int off = __shfl_sync(0xffffffffu, myoff, b + j);
                const float4 k4 = *(const float4*)(Kb + off);
                float sc = k4.x * q4.x + k4.y * q4.y + k4.z * q4.z + k4.w * q4.w;
                sc += __shfl_xor_sync(0xffffffffu, sc, 1);
                sc += __shfl_xor_sync(0xffffffffu, sc, 2);
                sc += __shfl_xor_sync(0xffffffffu, sc, 4);
                float p = __expf(sc);
                p = (b + j < cnt) ? p : 0.f;
                const float4 v4 = *(const float4*)(Vb + off);
                d += p;
                acc.x = fmaf(p, v4.x, acc.x);
                acc.y = fmaf(p, v4.y, acc.y);
                acc.z = fmaf(p, v4.z, acc.z);
                acc.w = fmaf(p, v4.w, acc.w);
            }
        }
    }

    float inv = (d > 0.f) ? (1.f / d) : 0.f;
    float4 o = make_float4(acc.x * inv, acc.y * inv, acc.z * inv, acc.w * inv);
    *(float4*)&out[(long)gw * DD + lane * 4] = o;
}

// ---------------- launch ----------------------------------------------------
extern "C" void kernel_launch(void* const* d_in, const int* in_sizes, int n_in,
                              void* d_out, int out_size) {
    const float* x  = (const float*)d_in[0];
    const float* Wk = (const float*)d_in[1];
    const float* bk = (const float*)d_in[2];
    const float* Wq = (const float*)d_in[3];
    const float* bq = (const float*)d_in[4];
    const float* Wv = (const float*)d_in[5];
    const float* bv = (const float*)d_in[6];
    const int*  src = (const int*)d_in[7];
    const int*  dst = (const int*)d_in[8];
    float* out = (float*)d_out;

    int n = in_sizes[0] / DD;   // 50000
    int E = in_sizes[7];        // 1600000

    prep_w<<<(3 * DD * DD + 255) / 256, 256>>>(Wk, Wq, Wv);

    cudaFuncSetAttribute(proj_wmma, cudaFuncAttributeMaxDynamicSharedMemorySize,
                         PS_TOT);
    dim3 pg((n + 63) / 64, 3);
    proj_wmma<<<pg, 256, PS_TOT>>>(x, bk, bq, bv, n);

    hist_kernel<<<(E + 255) / 256, 256>>>(dst, E);
    scan_chain_kernel<<<(n + 1023) / 1024, 1024>>>(n);
    fill_kernel<<<(E + 255) / 256, 256>>>(src, dst, E);

    int totalThreads = n * 32;
    aggregate_kernel<<<(totalThreads + 255) / 256, 256>>>(out, n);
}

// round 11
// speedup vs baseline: 1.4930x; 1.2459x over previous
#include <cuda_runtime.h>
#include <cuda_fp16.h>
#include <mma.h>
#include <math_constants.h>
#include <cstdint>

using namespace nvcuda;

#define DD   128
#define MAXN 50048
#define MAXE 1600256

// ---------------- device scratch (no allocations allowed) ----------------
__device__ __align__(128) float  g_K [MAXN * DD];
__device__ __align__(128) float  g_Q [MAXN * DD];
__device__ __align__(128) __half g_Vh[MAXN * DD];
__device__ __align__(128) __half g_Whi[3 * DD * DD];
__device__ __align__(128) __half g_Wlo[3 * DD * DD];
__device__ int g_deg[MAXN];
__device__ int g_off[MAXN + 1];
__device__ int g_pos[MAXN];
__device__ int g_esrc[MAXE];        // BYTE offsets into g_K (src * 512)
__device__ int g_chain[64];

// ---------------- prep: split W hi/lo + zero g_deg --------------------------
__global__ void prep_w(const float* __restrict__ Wk,
                       const float* __restrict__ Wq,
                       const float* __restrict__ Wv, int n) {
    int idx = blockIdx.x * blockDim.x + threadIdx.x;
    if (idx < n) g_deg[idx] = 0;
    if (idx >= 3 * DD * DD) return;
    int which = idx / (DD * DD);
    int i     = idx - which * (DD * DD);
    const float* W = (which == 0) ? Wk : (which == 1) ? Wq : Wv;
    float v  = W[i];
    __half h = __float2half_rn(v);
    __half l = __float2half_rn(v - __half2float(h));
    g_Whi[idx] = h;
    g_Wlo[idx] = l;
}

// ---------------- projection via wmma, 2 CTAs/SM ----------------------------
#define LDH  136
#define LDO  132
#define SA_BYTES  (64 * LDH * 2)
#define SB_BYTES  (128 * LDH * 2)
#define PS_AHI    0
#define PS_ALO    (SA_BYTES)
#define PS_BHI    (2 * SA_BYTES)
#define PS_BLO    (2 * SA_BYTES + SB_BYTES)
#define PS_TOT    (2 * SA_BYTES + 2 * SB_BYTES)

__global__ void __launch_bounds__(256, 2)
proj_wmma(const float* __restrict__ X,
          const float* __restrict__ bk,
          const float* __restrict__ bq,
          const float* __restrict__ bv,
          int n) {
    extern __shared__ char smem[];
    __half* sAhi = (__half*)(smem + PS_AHI);
    __half* sAlo = (__half*)(smem + PS_ALO);
    __half* sBhi = (__half*)(smem + PS_BHI);
    __half* sBlo = (__half*)(smem + PS_BLO);
    float*  sOut = (float*)(smem);

    const int tid = threadIdx.x, wid = tid >> 5;
    const int wr = wid >> 2, wc = wid & 3;
    const int which = blockIdx.y;
    const int m0 = blockIdx.x * 64;

    for (int idx = tid; idx < 64 * 32; idx += 256) {
        int row = idx >> 5;
        int c0  = (idx & 31) << 2;
        int gr  = m0 + row;
        float4 v = (gr < n) ? *(const float4*)&X[(long)gr * DD + c0]
                            : make_float4(0.f, 0.f, 0.f, 0.f);
        __half h0 = __float2half_rn(v.x), h1 = __float2half_rn(v.y);
        __half h2 = __float2half_rn(v.z), h3 = __float2half_rn(v.w);
        __half l0 = __float2half_rn(v.x - __half2float(h0));
        __half l1 = __float2half_rn(v.y - __half2float(h1));
        __half l2 = __float2half_rn(v.z - __half2float(h2));
        __half l3 = __float2half_rn(v.w - __half2float(h3));
        __half2 H01 = __halves2half2(h0, h1), H23 = __halves2half2(h2, h3);
        __half2 L01 = __halves2half2(l0, l1), L23 = __halves2half2(l2, l3);
        uint2 uh; uh.x = *(uint32_t*)&H01; uh.y = *(uint32_t*)&H23;
        uint2 ul; ul.x = *(uint32_t*)&L01; ul.y = *(uint32_t*)&L23;
        *(uint2*)&sAhi[row * LDH + c0] = uh;
        *(uint2*)&sAlo[row * LDH + c0] = ul;
    }

    {
        const uint4* ghi = (const uint4*)(g_Whi + which * (DD * DD));
        const uint4* glo = (const uint4*)(g_Wlo + which * (DD * DD));
        for (int idx = tid; idx < 128 * 16; idx += 256) {
            int c  = idx >> 4;
            int kq = (idx & 15) << 3;
            uint4 vh = ghi[idx];
            uint4 vl = glo[idx];
            *(uint4*)&sBhi[c * LDH + kq] = vh;
            *(uint4*)&sBlo[c * LDH + kq] = vl;
        }
    }
    __syncthreads();

    wmma::fragment<wmma::accumulator, 16, 16, 16, float> acc[2][2];
#pragma unroll
    for (int i = 0; i < 2; i++)
#pragma unroll
        for (int j = 0; j < 2; j++) wmma::fill_fragment(acc[i][j], 0.f);

#pragma unroll
    for (int k0 = 0; k0 < 128; k0 += 16) {
        wmma::fragment<wmma::matrix_a, 16, 16, 16, __half, wmma::row_major> ah[2], al[2];
#pragma unroll
        for (int i = 0; i < 2; i++) {
            wmma::load_matrix_sync(ah[i], sAhi + (wr * 32 + i * 16) * LDH + k0, LDH);
            wmma::load_matrix_sync(al[i], sAlo + (wr * 32 + i * 16) * LDH + k0, LDH);
        }
#pragma unroll
        for (int j = 0; j < 2; j++) {
            wmma::fragment<wmma::matrix_b, 16, 16, 16, __half, wmma::col_major> bh, bl;
            wmma::load_matrix_sync(bh, sBhi + (wc * 32 + j * 16) * LDH + k0, LDH);
            wmma::load_matrix_sync(bl, sBlo + (wc * 32 + j * 16) * LDH + k0, LDH);
#pragma unroll
            for (int i = 0; i < 2; i++) {
                wmma::mma_sync(acc[i][j], ah[i], bh, acc[i][j]);
                wmma::mma_sync(acc[i][j], ah[i], bl, acc[i][j]);
                wmma::mma_sync(acc[i][j], al[i], bh, acc[i][j]);
            }
        }
    }

    __syncthreads();
#pragma unroll
    for (int i = 0; i < 2; i++)
#pragma unroll
        for (int j = 0; j < 2; j++)
            wmma::store_matrix_sync(&sOut[(wr * 32 + i * 16) * LDO + wc * 32 + j * 16],
                                    acc[i][j], LDO, wmma::mem_row_major);
    __syncthreads();

    const float* b = (which == 0) ? bk : (which == 1) ? bq : bv;
    for (int idx = tid; idx < 64 * 32; idx += 256) {
        int row = idx >> 5;
        int c0  = (idx & 31) << 2;
        int gr  = m0 + row;
        if (gr < n) {
            float4 o  = *(const float4*)&sOut[row * LDO + c0];
            float4 bb = *(const float4*)&b[c0];
            o.x += bb.x; o.y += bb.y; o.z += bb.z; o.w += bb.w;
            if (which == 2) {
                __half2 h01 = __halves2half2(__float2half_rn(o.x), __float2half_rn(o.y));
                __half2 h23 = __halves2half2(__float2half_rn(o.z), __float2half_rn(o.w));
                uint2 u; u.x = *(uint32_t*)&h01; u.y = *(uint32_t*)&h23;
                *(uint2*)&g_Vh[(long)gr * DD + c0] = u;
            } else {
                float* __restrict__ Y = (which == 0) ? g_K : g_Q;
                *(float4*)&Y[(long)gr * DD + c0] = o;
            }
        }
    }
}

// ---------------- CSR build -------------------------------------------------
__global__ void hist_kernel(const int* __restrict__ dst, int E) {
    int e = blockIdx.x * blockDim.x + threadIdx.x;
    if (e < 64) g_chain[e] = 0;
    if (e < E) atomicAdd(&g_deg[dst[e]], 1);
}

__global__ void __launch_bounds__(1024, 1)
scan_chain_kernel(int n) {
    __shared__ int wsum[32];
    __shared__ int s_total, s_prefix;

    const int tid  = threadIdx.x;
    const int lane = tid & 31, warp = tid >> 5;
    const int i    = blockIdx.x * 1024 + tid;

    int v = (i < n) ? g_deg[i] : 0;

    int inc = v;
#pragma unroll
    for (int o = 1; o < 32; o <<= 1) {
        int t = __shfl_up_sync(0xffffffffu, inc, o);
        if (lane >= o) inc += t;
    }
    if (lane == 31) wsum[warp] = inc;
    __syncthreads();

    if (warp == 0) {
        int w  = wsum[lane];
        int wi = w;
#pragma unroll
        for (int o = 1; o < 32; o <<= 1) {
            int t = __shfl_up_sync(0xffffffffu, wi, o);
            if (lane >= o) wi += t;
        }
        wsum[lane] = wi - w;
        if (lane == 31) s_total = wi;
    }
    __syncthreads();

    const int excl = (inc - v) + wsum[warp];

    if (tid == 0) {
        int prefix = 0;
        if (blockIdx.x > 0) {
            int f;
            do { f = atomicAdd(&g_chain[blockIdx.x - 1], 0); } while (f == 0);
            prefix = f - 1;
        }
        atomicExch(&g_chain[blockIdx.x], prefix + s_total + 1);
        s_prefix = prefix;
    }
    __syncthreads();

    if (i < n) {
        int o = s_prefix + excl;
        g_off[i] = o;
        g_pos[i] = o;
    }
    if (blockIdx.x == gridDim.x - 1 && tid == 0)
        g_off[n] = s_prefix + s_total;
}

__global__ void fill_kernel(const int* __restrict__ src,
                            const int* __restrict__ dst, int E) {
    int e = blockIdx.x * blockDim.x + threadIdx.x;
    if (e < E) {
        int p = atomicAdd(&g_pos[dst[e]], 1);
        g_esrc[p] = src[e] << 9;     // byte offset in g_K (fp32 rows)
    }
}

// ---------------- fused edge-softmax + aggregate ----------------------------
// K fp32 (16B/lane), V fp16 (8B/lane). No online max (scores bounded ~32).
__global__ void aggregate_kernel(float* __restrict__ out, int n) {
    int gw   = (blockIdx.x * blockDim.x + threadIdx.x) >> 5;
    int lane = threadIdx.x & 31;
    if (gw >= n) return;

    const int beg = g_off[gw];
    const int end = g_off[gw + 1];

    const char* Kb = (const char*)g_K  + lane * 16;
    const char* Vb = (const char*)g_Vh + lane * 8;
    const float4 q4 = *(const float4*)&g_Q[(long)gw * DD + lane * 4];

    float  d = 0.f;
    float4 acc = make_float4(0.f, 0.f, 0.f, 0.f);

    for (int e0 = beg; e0 < end; e0 += 32) {
        int myoff = (e0 + lane < end) ? g_esrc[e0 + lane] : 0;
        int cnt   = min(32, end - e0);

        for (int b = 0; b < cnt; b += 8) {
#pragma unroll
            for (int j = 0; j < 8; j++) {
                int off = __shfl_sync(0xffffffffu, myoff, b + j);
                const float4 k4 = *(const float4*)(Kb + off);
                float sc = k4.x * q4.x + k4.y * q4.y + k4.z * q4.z + k4.w * q4.w;
                sc += __shfl_xor_sync(0xffffffffu, sc, 1);
                sc += __shfl_xor_sync(0xffffffffu, sc, 2);
                sc += __shfl_xor_sync(0xffffffffu, sc, 4);
                float p = __expf(sc);
                p = (b + j < cnt) ? p : 0.f;
                uint2 vraw = *(const uint2*)(Vb + (off >> 1));
                float2 va = __half22float2(*reinterpret_cast<const __half2*>(&vraw.x));
                float2 vb = __half22float2(*reinterpret_cast<const __half2*>(&vraw.y));
                d += p;
                acc.x = fmaf(p, va.x, acc.x);
                acc.y = fmaf(p, va.y, acc.y);
                acc.z = fmaf(p, vb.x, acc.z);
                acc.w = fmaf(p, vb.y, acc.w);
            }
        }
    }

    float inv = (d > 0.f) ? (1.f / d) : 0.f;
    float4 o = make_float4(acc.x * inv, acc.y * inv, acc.z * inv, acc.w * inv);
    *(float4*)&out[(long)gw * DD + lane * 4] = o;
}

// ---------------- launch ----------------------------------------------------
extern "C" void kernel_launch(void* const* d_in, const int* in_sizes, int n_in,
                              void* d_out, int out_size) {
    const float* x  = (const float*)d_in[0];
    const float* Wk = (const float*)d_in[1];
    const float* bk = (const float*)d_in[2];
    const float* Wq = (const float*)d_in[3];
    const float* bq = (const float*)d_in[4];
    const float* Wv = (const float*)d_in[5];
    const float* bv = (const float*)d_in[6];
    const int*  src = (const int*)d_in[7];
    const int*  dst = (const int*)d_in[8];
    float* out = (float*)d_out;

    int n = in_sizes[0] / DD;   // 50000
    int E = in_sizes[7];        // 1600000

    int prepN = (n > 3 * DD * DD) ? n : 3 * DD * DD;
    prep_w<<<(prepN + 255) / 256, 256>>>(Wk, Wq, Wv, n);        // 1
    hist_kernel<<<(E + 255) / 256, 256>>>(dst, E);              // 2
    scan_chain_kernel<<<(n + 1023) / 1024, 1024>>>(n);          // 3

    cudaFuncSetAttribute(proj_wmma, cudaFuncAttributeMaxDynamicSharedMemorySize,
                         PS_TOT);
    dim3 pg((n + 63) / 64, 3);
    proj_wmma<<<pg, 256, PS_TOT>>>(x, bk, bq, bv, n);           // 4 <- ncu slot

    fill_kernel<<<(E + 255) / 256, 256>>>(src, dst, E);         // 5

    int totalThreads = n * 32;
    aggregate_kernel<<<(totalThreads + 255) / 256, 256>>>(out, n);  // 6
}

// round 12
// speedup vs baseline: 1.5286x; 1.0239x over previous
#include <cuda_runtime.h>
#include <cuda_fp16.h>
#include <mma.h>
#include <math_constants.h>
#include <cstdint>

using namespace nvcuda;

#define DD   128
#define MAXN 50048
#define MAXE 1600256

// ---------------- device scratch (no allocations allowed) ----------------
__device__ __align__(128) float  g_K [MAXN * DD];
__device__ __align__(128) float  g_Q [MAXN * DD];
__device__ __align__(128) __half g_Vh[MAXN * DD];
__device__ __align__(128) __half g_Whi[3 * DD * DD];
__device__ __align__(128) __half g_Wlo[3 * DD * DD];
__device__ int g_deg[MAXN];
__device__ int g_off[MAXN + 1];
__device__ int g_pos[MAXN];
__device__ int g_esrc[MAXE];        // BYTE offsets into g_K (src * 512)
__device__ int g_chain[64];

// ---------------- prep: split W hi/lo + zero g_deg + chain flags ------------
__global__ void prep_w(const float* __restrict__ Wk,
                       const float* __restrict__ Wq,
                       const float* __restrict__ Wv, int n) {
    int idx = blockIdx.x * blockDim.x + threadIdx.x;
    if (idx < 64) g_chain[idx] = 0;
    if (idx < n) g_deg[idx] = 0;
    if (idx >= 3 * DD * DD) return;
    int which = idx / (DD * DD);
    int i     = idx - which * (DD * DD);
    const float* W = (which == 0) ? Wk : (which == 1) ? Wq : Wv;
    float v  = W[i];
    __half h = __float2half_rn(v);
    __half l = __float2half_rn(v - __half2float(h));
    g_Whi[idx] = h;
    g_Wlo[idx] = l;
}

// ---------------- projection via wmma, 2 CTAs/SM (unchanged r11) ------------
#define LDH  136
#define LDO  132
#define SA_BYTES  (64 * LDH * 2)
#define SB_BYTES  (128 * LDH * 2)
#define PS_AHI    0
#define PS_ALO    (SA_BYTES)
#define PS_BHI    (2 * SA_BYTES)
#define PS_BLO    (2 * SA_BYTES + SB_BYTES)
#define PS_TOT    (2 * SA_BYTES + 2 * SB_BYTES)

__global__ void __launch_bounds__(256, 2)
proj_wmma(const float* __restrict__ X,
          const float* __restrict__ bk,
          const float* __restrict__ bq,
          const float* __restrict__ bv,
          int n) {
    extern __shared__ char smem[];
    __half* sAhi = (__half*)(smem + PS_AHI);
    __half* sAlo = (__half*)(smem + PS_ALO);
    __half* sBhi = (__half*)(smem + PS_BHI);
    __half* sBlo = (__half*)(smem + PS_BLO);
    float*  sOut = (float*)(smem);

    const int tid = threadIdx.x, wid = tid >> 5;
    const int wr = wid >> 2, wc = wid & 3;
    const int which = blockIdx.y;
    const int m0 = blockIdx.x * 64;

    for (int idx = tid; idx < 64 * 32; idx += 256) {
        int row = idx >> 5;
        int c0  = (idx & 31) << 2;
        int gr  = m0 + row;
        float4 v = (gr < n) ? *(const float4*)&X[(long)gr * DD + c0]
                            : make_float4(0.f, 0.f, 0.f, 0.f);
        __half h0 = __float2half_rn(v.x), h1 = __float2half_rn(v.y);
        __half h2 = __float2half_rn(v.z), h3 = __float2half_rn(v.w);
        __half l0 = __float2half_rn(v.x - __half2float(h0));
        __half l1 = __float2half_rn(v.y - __half2float(h1));
        __half l2 = __float2half_rn(v.z - __half2float(h2));
        __half l3 = __float2half_rn(v.w - __half2float(h3));
        __half2 H01 = __halves2half2(h0, h1), H23 = __halves2half2(h2, h3);
        __half2 L01 = __halves2half2(l0, l1), L23 = __halves2half2(l2, l3);
        uint2 uh; uh.x = *(uint32_t*)&H01; uh.y = *(uint32_t*)&H23;
        uint2 ul; ul.x = *(uint32_t*)&L01; ul.y = *(uint32_t*)&L23;
        *(uint2*)&sAhi[row * LDH + c0] = uh;
        *(uint2*)&sAlo[row * LDH + c0] = ul;
    }

    {
        const uint4* ghi = (const uint4*)(g_Whi + which * (DD * DD));
        const uint4* glo = (const uint4*)(g_Wlo + which * (DD * DD));
        for (int idx = tid; idx < 128 * 16; idx += 256) {
            int c  = idx >> 4;
            int kq = (idx & 15) << 3;
            uint4 vh = ghi[idx];
            uint4 vl = glo[idx];
            *(uint4*)&sBhi[c * LDH + kq] = vh;
            *(uint4*)&sBlo[c * LDH + kq] = vl;
        }
    }
    __syncthreads();

    wmma::fragment<wmma::accumulator, 16, 16, 16, float> acc[2][2];
#pragma unroll
    for (int i = 0; i < 2; i++)
#pragma unroll
        for (int j = 0; j < 2; j++) wmma::fill_fragment(acc[i][j], 0.f);

#pragma unroll
    for (int k0 = 0; k0 < 128; k0 += 16) {
        wmma::fragment<wmma::matrix_a, 16, 16, 16, __half, wmma::row_major> ah[2], al[2];
#pragma unroll
        for (int i = 0; i < 2; i++) {
            wmma::load_matrix_sync(ah[i], sAhi + (wr * 32 + i * 16) * LDH + k0, LDH);
            wmma::load_matrix_sync(al[i], sAlo + (wr * 32 + i * 16) * LDH + k0, LDH);
        }
#pragma unroll
        for (int j = 0; j < 2; j++) {
            wmma::fragment<wmma::matrix_b, 16, 16, 16, __half, wmma::col_major> bh, bl;
            wmma::load_matrix_sync(bh, sBhi + (wc * 32 + j * 16) * LDH + k0, LDH);
            wmma::load_matrix_sync(bl, sBlo + (wc * 32 + j * 16) * LDH + k0, LDH);
#pragma unroll
            for (int i = 0; i < 2; i++) {
                wmma::mma_sync(acc[i][j], ah[i], bh, acc[i][j]);
                wmma::mma_sync(acc[i][j], ah[i], bl, acc[i][j]);
                wmma::mma_sync(acc[i][j], al[i], bh, acc[i][j]);
            }
        }
    }

    __syncthreads();
#pragma unroll
    for (int i = 0; i < 2; i++)
#pragma unroll
        for (int j = 0; j < 2; j++)
            wmma::store_matrix_sync(&sOut[(wr * 32 + i * 16) * LDO + wc * 32 + j * 16],
                                    acc[i][j], LDO, wmma::mem_row_major);
    __syncthreads();

    const float* b = (which == 0) ? bk : (which == 1) ? bq : bv;
    for (int idx = tid; idx < 64 * 32; idx += 256) {
        int row = idx >> 5;
        int c0  = (idx & 31) << 2;
        int gr  = m0 + row;
        if (gr < n) {
            float4 o  = *(const float4*)&sOut[row * LDO + c0];
            float4 bb = *(const float4*)&b[c0];
            o.x += bb.x; o.y += bb.y; o.z += bb.z; o.w += bb.w;
            if (which == 2) {
                __half2 h01 = __halves2half2(__float2half_rn(o.x), __float2half_rn(o.y));
                __half2 h23 = __halves2half2(__float2half_rn(o.z), __float2half_rn(o.w));
                uint2 u; u.x = *(uint32_t*)&h01; u.y = *(uint32_t*)&h23;
                *(uint2*)&g_Vh[(long)gr * DD + c0] = u;
            } else {
                float* __restrict__ Y = (which == 0) ? g_K : g_Q;
                *(float4*)&Y[(long)gr * DD + c0] = o;
            }
        }
    }
}

// ---------------- CSR build: MLP=4 hist & fill -------------------------------
__global__ void hist_kernel(const int* __restrict__ dst, int E) {
    int base = blockIdx.x * 1024 + threadIdx.x;
#pragma unroll
    for (int i = 0; i < 4; i++) {
        int e = base + i * 256;
        if (e < E) atomicAdd(&g_deg[dst[e]], 1);
    }
}

__global__ void __launch_bounds__(1024, 1)
scan_chain_kernel(int n) {
    __shared__ int wsum[32];
    __shared__ int s_total, s_prefix;

    const int tid  = threadIdx.x;
    const int lane = tid & 31, warp = tid >> 5;
    const int i    = blockIdx.x * 1024 + tid;

    int v = (i < n) ? g_deg[i] : 0;

    int inc = v;
#pragma unroll
    for (int o = 1; o < 32; o <<= 1) {
        int t = __shfl_up_sync(0xffffffffu, inc, o);
        if (lane >= o) inc += t;
    }
    if (lane == 31) wsum[warp] = inc;
    __syncthreads();

    if (warp == 0) {
        int w  = wsum[lane];
        int wi = w;
#pragma unroll
        for (int o = 1; o < 32; o <<= 1) {
            int t = __shfl_up_sync(0xffffffffu, wi, o);
            if (lane >= o) wi += t;
        }
        wsum[lane] = wi - w;
        if (lane == 31) s_total = wi;
    }
    __syncthreads();

    const int excl = (inc - v) + wsum[warp];

    if (tid == 0) {
        int prefix = 0;
        if (blockIdx.x > 0) {
            int f;
            do { f = atomicAdd(&g_chain[blockIdx.x - 1], 0); } while (f == 0);
            prefix = f - 1;
        }
        atomicExch(&g_chain[blockIdx.x], prefix + s_total + 1);
        s_prefix = prefix;
    }
    __syncthreads();

    if (i < n) {
        int o = s_prefix + excl;
        g_off[i] = o;
        g_pos[i] = o;
    }
    if (blockIdx.x == gridDim.x - 1 && tid == 0)
        g_off[n] = s_prefix + s_total;
}

__global__ void fill_kernel(const int* __restrict__ src,
                            const int* __restrict__ dst, int E) {
    int base = blockIdx.x * 1024 + threadIdx.x;
#pragma unroll
    for (int i = 0; i < 4; i++) {
        int e = base + i * 256;
        if (e < E) {
            int p = atomicAdd(&g_pos[dst[e]], 1);
            g_esrc[p] = src[e] << 9;
        }
    }
}

// ---------------- fused edge-softmax + aggregate (occ-boosted) --------------
__global__ void __launch_bounds__(256, 6)
aggregate_kernel(float* __restrict__ out, int n) {
    int gw   = (blockIdx.x * blockDim.x + threadIdx.x) >> 5;
    int lane = threadIdx.x & 31;
    if (gw >= n) return;

    const int beg = g_off[gw];
    const int end = g_off[gw + 1];

    const char* Kb = (const char*)g_K  + lane * 16;
    const char* Vb = (const char*)g_Vh + lane * 8;
    const float4 q4 = *(const float4*)&g_Q[(long)gw * DD + lane * 4];

    float  d = 0.f;
    float4 acc = make_float4(0.f, 0.f, 0.f, 0.f);

    for (int e0 = beg; e0 < end; e0 += 32) {
        int myoff = (e0 + lane < end) ? g_esrc[e0 + lane] : 0;
        int cnt   = min(32, end - e0);

        for (int b = 0; b < cnt; b += 8) {
#pragma unroll
            for (int j = 0; j < 8; j++) {
                int off = __shfl_sync(0xffffffffu, myoff, b + j);
                const float4 k4 = *(const float4*)(Kb + off);
                float sc = k4.x * q4.x + k4.y * q4.y + k4.z * q4.z + k4.w * q4.w;
                sc += __shfl_xor_sync(0xffffffffu, sc, 1);
                sc += __shfl_xor_sync(0xffffffffu, sc, 2);
                sc += __shfl_xor_sync(0xffffffffu, sc, 4);
                float p = __expf(sc);
                p = (b + j < cnt) ? p : 0.f;
                uint2 vraw = *(const uint2*)(Vb + (off >> 1));
                float2 va = __half22float2(*reinterpret_cast<const __half2*>(&vraw.x));
                float2 vb = __half22float2(*reinterpret_cast<const __half2*>(&vraw.y));
                d += p;
                acc.x = fmaf(p, va.x, acc.x);
                acc.y = fmaf(p, va.y, acc.y);
                acc.z = fmaf(p, vb.x, acc.z);
                acc.w = fmaf(p, vb.y, acc.w);
            }
        }
    }

    float inv = (d > 0.f) ? (1.f / d) : 0.f;
    float4 o = make_float4(acc.x * inv, acc.y * inv, acc.z * inv, acc.w * inv);
    *(float4*)&out[(long)gw * DD + lane * 4] = o;
}

// ---------------- launch ----------------------------------------------------
extern "C" void kernel_launch(void* const* d_in, const int* in_sizes, int n_in,
                              void* d_out, int out_size) {
    const float* x  = (const float*)d_in[0];
    const float* Wk = (const float*)d_in[1];
    const float* bk = (const float*)d_in[2];
    const float* Wq = (const float*)d_in[3];
    const float* bq = (const float*)d_in[4];
    const float* Wv = (const float*)d_in[5];
    const float* bv = (const float*)d_in[6];
    const int*  src = (const int*)d_in[7];
    const int*  dst = (const int*)d_in[8];
    float* out = (float*)d_out;

    int n = in_sizes[0] / DD;   // 50000
    int E = in_sizes[7];        // 1600000

    int prepN = (n > 3 * DD * DD) ? n : 3 * DD * DD;
    prep_w<<<(prepN + 255) / 256, 256>>>(Wk, Wq, Wv, n);        // 1
    hist_kernel<<<(E + 1023) / 1024, 256>>>(dst, E);            // 2
    scan_chain_kernel<<<(n + 1023) / 1024, 1024>>>(n);          // 3
    fill_kernel<<<(E + 1023) / 1024, 256>>>(src, dst, E);       // 4 <- ncu slot

    cudaFuncSetAttribute(proj_wmma, cudaFuncAttributeMaxDynamicSharedMemorySize,
                         PS_TOT);
    dim3 pg((n + 63) / 64, 3);
    proj_wmma<<<pg, 256, PS_TOT>>>(x, bk, bq, bv, n);           // 5

    int totalThreads = n * 32;
    aggregate_kernel<<<(totalThreads + 255) / 256, 256>>>(out, n);  // 6
}

// round 13
// speedup vs baseline: 1.6003x; 1.0469x over previous
#include <cuda_runtime.h>
#include <cuda_fp16.h>
#include <mma.h>
#include <math_constants.h>
#include <cstdint>

using namespace nvcuda;

#define DD   128
#define MAXN 50048
#define MAXE 1600256

// ---------------- device scratch (no allocations allowed) ----------------
__device__ __align__(128) float  g_K [MAXN * DD];
__device__ __align__(128) float  g_Q [MAXN * DD];
__device__ __align__(128) __half g_Vh[MAXN * DD];
__device__ __align__(128) __half g_Whi[3 * DD * DD];
__device__ __align__(128) __half g_Wlo[3 * DD * DD];
__device__ int g_deg[MAXN];
__device__ int g_off[MAXN + 1];
__device__ int g_pos[MAXN];
__device__ int g_esrc[MAXE];        // BYTE offsets into g_K (src * 512)
__device__ int g_chain[64];

// ---------------- prep: split W hi/lo + zero g_deg + chain flags ------------
__global__ void prep_w(const float* __restrict__ Wk,
                       const float* __restrict__ Wq,
                       const float* __restrict__ Wv, int n) {
    int idx = blockIdx.x * blockDim.x + threadIdx.x;
    if (idx < 64) g_chain[idx] = 0;
    if (idx < n) g_deg[idx] = 0;
    if (idx >= 3 * DD * DD) return;
    int which = idx / (DD * DD);
    int i     = idx - which * (DD * DD);
    const float* W = (which == 0) ? Wk : (which == 1) ? Wq : Wv;
    float v  = W[i];
    __half h = __float2half_rn(v);
    __half l = __float2half_rn(v - __half2float(h));
    g_Whi[idx] = h;
    g_Wlo[idx] = l;
}

// ---------------- projection via wmma, 2 CTAs/SM (unchanged r12) ------------
#define LDH  136
#define LDO  132
#define SA_BYTES  (64 * LDH * 2)
#define SB_BYTES  (128 * LDH * 2)
#define PS_AHI    0
#define PS_ALO    (SA_BYTES)
#define PS_BHI    (2 * SA_BYTES)
#define PS_BLO    (2 * SA_BYTES + SB_BYTES)
#define PS_TOT    (2 * SA_BYTES + 2 * SB_BYTES)

__global__ void __launch_bounds__(256, 2)
proj_wmma(const float* __restrict__ X,
          const float* __restrict__ bk,
          const float* __restrict__ bq,
          const float* __restrict__ bv,
          int n) {
    extern __shared__ char smem[];
    __half* sAhi = (__half*)(smem + PS_AHI);
    __half* sAlo = (__half*)(smem + PS_ALO);
    __half* sBhi = (__half*)(smem + PS_BHI);
    __half* sBlo = (__half*)(smem + PS_BLO);
    float*  sOut = (float*)(smem);

    const int tid = threadIdx.x, wid = tid >> 5;
    const int wr = wid >> 2, wc = wid & 3;
    const int which = blockIdx.y;
    const int m0 = blockIdx.x * 64;

    for (int idx = tid; idx < 64 * 32; idx += 256) {
        int row = idx >> 5;
        int c0  = (idx & 31) << 2;
        int gr  = m0 + row;
        float4 v = (gr < n) ? *(const float4*)&X[(long)gr * DD + c0]
                            : make_float4(0.f, 0.f, 0.f, 0.f);
        __half h0 = __float2half_rn(v.x), h1 = __float2half_rn(v.y);
        __half h2 = __float2half_rn(v.z), h3 = __float2half_rn(v.w);
        __half l0 = __float2half_rn(v.x - __half2float(h0));
        __half l1 = __float2half_rn(v.y - __half2float(h1));
        __half l2 = __float2half_rn(v.z - __half2float(h2));
        __half l3 = __float2half_rn(v.w - __half2float(h3));
        __half2 H01 = __halves2half2(h0, h1), H23 = __halves2half2(h2, h3);
        __half2 L01 = __halves2half2(l0, l1), L23 = __halves2half2(l2, l3);
        uint2 uh; uh.x = *(uint32_t*)&H01; uh.y = *(uint32_t*)&H23;
        uint2 ul; ul.x = *(uint32_t*)&L01; ul.y = *(uint32_t*)&L23;
        *(uint2*)&sAhi[row * LDH + c0] = uh;
        *(uint2*)&sAlo[row * LDH + c0] = ul;
    }

    {
        const uint4* ghi = (const uint4*)(g_Whi + which * (DD * DD));
        const uint4* glo = (const uint4*)(g_Wlo + which * (DD * DD));
        for (int idx = tid; idx < 128 * 16; idx += 256) {
            int c  = idx >> 4;
            int kq = (idx & 15) << 3;
            uint4 vh = ghi[idx];
            uint4 vl = glo[idx];
            *(uint4*)&sBhi[c * LDH + kq] = vh;
            *(uint4*)&sBlo[c * LDH + kq] = vl;
        }
    }
    __syncthreads();

    wmma::fragment<wmma::accumulator, 16, 16, 16, float> acc[2][2];
#pragma unroll
    for (int i = 0; i < 2; i++)
#pragma unroll
        for (int j = 0; j < 2; j++) wmma::fill_fragment(acc[i][j], 0.f);

#pragma unroll
    for (int k0 = 0; k0 < 128; k0 += 16) {
        wmma::fragment<wmma::matrix_a, 16, 16, 16, __half, wmma::row_major> ah[2], al[2];
#pragma unroll
        for (int i = 0; i < 2; i++) {
            wmma::load_matrix_sync(ah[i], sAhi + (wr * 32 + i * 16) * LDH + k0, LDH);
            wmma::load_matrix_sync(al[i], sAlo + (wr * 32 + i * 16) * LDH + k0, LDH);
        }
#pragma unroll
        for (int j = 0; j < 2; j++) {
            wmma::fragment<wmma::matrix_b, 16, 16, 16, __half, wmma::col_major> bh, bl;
            wmma::load_matrix_sync(bh, sBhi + (wc * 32 + j * 16) * LDH + k0, LDH);
            wmma::load_matrix_sync(bl, sBlo + (wc * 32 + j * 16) * LDH + k0, LDH);
#pragma unroll
            for (int i = 0; i < 2; i++) {
                wmma::mma_sync(acc[i][j], ah[i], bh, acc[i][j]);
                wmma::mma_sync(acc[i][j], ah[i], bl, acc[i][j]);
                wmma::mma_sync(acc[i][j], al[i], bh, acc[i][j]);
            }
        }
    }

    __syncthreads();
#pragma unroll
    for (int i = 0; i < 2; i++)
#pragma unroll
        for (int j = 0; j < 2; j++)
            wmma::store_matrix_sync(&sOut[(wr * 32 + i * 16) * LDO + wc * 32 + j * 16],
                                    acc[i][j], LDO, wmma::mem_row_major);
    __syncthreads();

    const float* b = (which == 0) ? bk : (which == 1) ? bq : bv;
    for (int idx = tid; idx < 64 * 32; idx += 256) {
        int row = idx >> 5;
        int c0  = (idx & 31) << 2;
        int gr  = m0 + row;
        if (gr < n) {
            float4 o  = *(const float4*)&sOut[row * LDO + c0];
            float4 bb = *(const float4*)&b[c0];
            o.x += bb.x; o.y += bb.y; o.z += bb.z; o.w += bb.w;
            if (which == 2) {
                __half2 h01 = __halves2half2(__float2half_rn(o.x), __float2half_rn(o.y));
                __half2 h23 = __halves2half2(__float2half_rn(o.z), __float2half_rn(o.w));
                uint2 u; u.x = *(uint32_t*)&h01; u.y = *(uint32_t*)&h23;
                *(uint2*)&g_Vh[(long)gr * DD + c0] = u;
            } else {
                float* __restrict__ Y = (which == 0) ? g_K : g_Q;
                *(float4*)&Y[(long)gr * DD + c0] = o;
            }
        }
    }
}

// ---------------- CSR build (unchanged r12) ---------------------------------
__global__ void hist_kernel(const int* __restrict__ dst, int E) {
    int base = blockIdx.x * 1024 + threadIdx.x;
#pragma unroll
    for (int i = 0; i < 4; i++) {
        int e = base + i * 256;
        if (e < E) atomicAdd(&g_deg[dst[e]], 1);
    }
}

__global__ void __launch_bounds__(1024, 1)
scan_chain_kernel(int n) {
    __shared__ int wsum[32];
    __shared__ int s_total, s_prefix;

    const int tid  = threadIdx.x;
    const int lane = tid & 31, warp = tid >> 5;
    const int i    = blockIdx.x * 1024 + tid;

    int v = (i < n) ? g_deg[i] : 0;

    int inc = v;
#pragma unroll
    for (int o = 1; o < 32; o <<= 1) {
        int t = __shfl_up_sync(0xffffffffu, inc, o);
        if (lane >= o) inc += t;
    }
    if (lane == 31) wsum[warp] = inc;
    __syncthreads();

    if (warp == 0) {
        int w  = wsum[lane];
        int wi = w;
#pragma unroll
        for (int o = 1; o < 32; o <<= 1) {
            int t = __shfl_up_sync(0xffffffffu, wi, o);
            if (lane >= o) wi += t;
        }
        wsum[lane] = wi - w;
        if (lane == 31) s_total = wi;
    }
    __syncthreads();

    const int excl = (inc - v) + wsum[warp];

    if (tid == 0) {
        int prefix = 0;
        if (blockIdx.x > 0) {
            int f;
            do { f = atomicAdd(&g_chain[blockIdx.x - 1], 0); } while (f == 0);
            prefix = f - 1;
        }
        atomicExch(&g_chain[blockIdx.x], prefix + s_total + 1);
        s_prefix = prefix;
    }
    __syncthreads();

    if (i < n) {
        int o = s_prefix + excl;
        g_off[i] = o;
        g_pos[i] = o;
    }
    if (blockIdx.x == gridDim.x - 1 && tid == 0)
        g_off[n] = s_prefix + s_total;
}

__global__ void fill_kernel(const int* __restrict__ src,
                            const int* __restrict__ dst, int E) {
    int base = blockIdx.x * 1024 + threadIdx.x;
#pragma unroll
    for (int i = 0; i < 4; i++) {
        int e = base + i * 256;
        if (e < E) {
            int p = atomicAdd(&g_pos[dst[e]], 1);
            g_esrc[p] = src[e] << 9;
        }
    }
}

// ---------------- fused edge-softmax + aggregate (unchanged r12) ------------
__global__ void __launch_bounds__(256, 6)
aggregate_kernel(float* __restrict__ out, int n) {
    int gw   = (blockIdx.x * blockDim.x + threadIdx.x) >> 5;
    int lane = threadIdx.x & 31;
    if (gw >= n) return;

    const int beg = g_off[gw];
    const int end = g_off[gw + 1];

    const char* Kb = (const char*)g_K  + lane * 16;
    const char* Vb = (const char*)g_Vh + lane * 8;
    const float4 q4 = *(const float4*)&g_Q[(long)gw * DD + lane * 4];

    float  d = 0.f;
    float4 acc = make_float4(0.f, 0.f, 0.f, 0.f);

    for (int e0 = beg; e0 < end; e0 += 32) {
        int myoff = (e0 + lane < end) ? g_esrc[e0 + lane] : 0;
        int cnt   = min(32, end - e0);

        for (int b = 0; b < cnt; b += 8) {
#pragma unroll
            for (int j = 0; j < 8; j++) {
                int off = __shfl_sync(0xffffffffu, myoff, b + j);
                const float4 k4 = *(const float4*)(Kb + off);
                float sc = k4.x * q4.x + k4.y * q4.y + k4.z * q4.z + k4.w * q4.w;
                sc += __shfl_xor_sync(0xffffffffu, sc, 1);
                sc += __shfl_xor_sync(0xffffffffu, sc, 2);
                sc += __shfl_xor_sync(0xffffffffu, sc, 4);
                float p = __expf(sc);
                p = (b + j < cnt) ? p : 0.f;
                uint2 vraw = *(const uint2*)(Vb + (off >> 1));
                float2 va = __half22float2(*reinterpret_cast<const __half2*>(&vraw.x));
                float2 vb = __half22float2(*reinterpret_cast<const __half2*>(&vraw.y));
                d += p;
                acc.x = fmaf(p, va.x, acc.x);
                acc.y = fmaf(p, va.y, acc.y);
                acc.z = fmaf(p, vb.x, acc.z);
                acc.w = fmaf(p, vb.y, acc.w);
            }
        }
    }

    float inv = (d > 0.f) ? (1.f / d) : 0.f;
    float4 o = make_float4(acc.x * inv, acc.y * inv, acc.z * inv, acc.w * inv);
    *(float4*)&out[(long)gw * DD + lane * 4] = o;
}

// ---------------- launch: fork-join overlap of proj with CSR chain ----------
extern "C" void kernel_launch(void* const* d_in, const int* in_sizes, int n_in,
                              void* d_out, int out_size) {
    const float* x  = (const float*)d_in[0];
    const float* Wk = (const float*)d_in[1];
    const float* bk = (const float*)d_in[2];
    const float* Wq = (const float*)d_in[3];
    const float* bq = (const float*)d_in[4];
    const float* Wv = (const float*)d_in[5];
    const float* bv = (const float*)d_in[6];
    const int*  src = (const int*)d_in[7];
    const int*  dst = (const int*)d_in[8];
    float* out = (float*)d_out;

    int n = in_sizes[0] / DD;   // 50000
    int E = in_sizes[7];        // 1600000

    // side stream + fork/join events (created per call; handles are host-side
    // resources, no device allocations; not destroyed to keep capture valid)
    cudaStream_t s2;
    cudaStreamCreateWithFlags(&s2, cudaStreamNonBlocking);
    cudaEvent_t evF, evJ;
    cudaEventCreateWithFlags(&evF, cudaEventDisableTiming);
    cudaEventCreateWithFlags(&evJ, cudaEventDisableTiming);

    cudaFuncSetAttribute(proj_wmma, cudaFuncAttributeMaxDynamicSharedMemorySize,
                         PS_TOT);

    int prepN = (n > 3 * DD * DD) ? n : 3 * DD * DD;
    prep_w<<<(prepN + 255) / 256, 256>>>(Wk, Wq, Wv, n);     // stream 0

    // fork: proj on s2 (needs prep's W split), CSR chain stays on stream 0
    cudaEventRecord(evF, 0);
    cudaStreamWaitEvent(s2, evF, 0);
    dim3 pg((n + 63) / 64, 3);
    proj_wmma<<<pg, 256, PS_TOT, s2>>>(x, bk, bq, bv, n);

    hist_kernel<<<(E + 1023) / 1024, 256>>>(dst, E);
    scan_chain_kernel<<<(n + 1023) / 1024, 1024>>>(n);
    fill_kernel<<<(E + 1023) / 1024, 256>>>(src, dst, E);

    // join: aggregate needs both branches
    cudaEventRecord(evJ, s2);
    cudaStreamWaitEvent(0, evJ, 0);

    int totalThreads = n * 32;
    aggregate_kernel<<<(totalThreads + 255) / 256, 256>>>(out, n);
}